// round 13
// baseline (speedup 1.0000x reference)
#include <cuda_runtime.h>
#include <cuda_bf16.h>
#include <cstdint>

#define B_  2
#define S_  2048
#define D_  1024
#define H_  16
#define DK_ 64
#define NEGV -1.0e9f

// Scratch (allocation-free rule: __device__ globals)
__device__ float g_q[B_ * S_ * D_];
__device__ float g_k[B_ * S_ * D_];
__device__ float g_v[B_ * S_ * D_];
__device__ float g_ctx[B_ * S_ * D_];

// ===========================================================================
// Common helpers
// ===========================================================================
#define MMA16816(c, a, b) \
    asm volatile("mma.sync.aligned.m16n8k16.row.col.f32.bf16.bf16.f32 " \
        "{%0,%1,%2,%3}, {%4,%5,%6,%7}, {%8,%9}, {%0,%1,%2,%3};" \
        : "+f"((c)[0]), "+f"((c)[1]), "+f"((c)[2]), "+f"((c)[3]) \
        : "r"((a)[0]), "r"((a)[1]), "r"((a)[2]), "r"((a)[3]), \
          "r"((b)[0]), "r"((b)[1]))

#define LDSM_X4(d, addr) \
    asm volatile("ldmatrix.sync.aligned.m8n8.x4.shared.b16 {%0,%1,%2,%3}, [%4];" \
        : "=r"((d)[0]), "=r"((d)[1]), "=r"((d)[2]), "=r"((d)[3]) : "r"(addr))

#define LDSM_X2(d, addr) \
    asm volatile("ldmatrix.sync.aligned.m8n8.x2.shared.b16 {%0,%1}, [%2];" \
        : "=r"((d)[0]), "=r"((d)[1]) : "r"(addr))

#define LDSM_X2T(d, addr) \
    asm volatile("ldmatrix.sync.aligned.m8n8.x2.trans.shared.b16 {%0,%1}, [%2];" \
        : "=r"((d)[0]), "=r"((d)[1]) : "r"(addr))

__device__ __forceinline__ uint32_t smem_u32(const void* p) {
    uint32_t a;
    asm("{ .reg .u64 t; cvta.to.shared.u64 t, %1; cvt.u32.u64 %0, t; }"
        : "=r"(a) : "l"(p));
    return a;
}

// Convert 16 fp32 (4 float4) -> 16 bf16 hi + 16 bf16 lo via cvt.rn.bf16x2.
__device__ __forceinline__ void store_split16(
    const float4* v, char* hi, char* lo, uint32_t boff)
{
    uint32_t hw[8], lw[8];
#pragma unroll
    for (int q = 0; q < 4; q++) {
        __nv_bfloat162 h0 = __floats2bfloat162_rn(v[q].x, v[q].y);
        __nv_bfloat162 h1 = __floats2bfloat162_rn(v[q].z, v[q].w);
        float2 f0 = __bfloat1622float2(h0);
        float2 f1 = __bfloat1622float2(h1);
        __nv_bfloat162 l0 = __floats2bfloat162_rn(v[q].x - f0.x, v[q].y - f0.y);
        __nv_bfloat162 l1 = __floats2bfloat162_rn(v[q].z - f1.x, v[q].w - f1.y);
        hw[q * 2]     = *(const uint32_t*)&h0;
        hw[q * 2 + 1] = *(const uint32_t*)&h1;
        lw[q * 2]     = *(const uint32_t*)&l0;
        lw[q * 2 + 1] = *(const uint32_t*)&l1;
    }
    *(uint4*)(hi + boff)      = make_uint4(hw[0], hw[1], hw[2], hw[3]);
    *(uint4*)(hi + boff + 16) = make_uint4(hw[4], hw[5], hw[6], hw[7]);
    *(uint4*)(lo + boff)      = make_uint4(lw[0], lw[1], lw[2], lw[3]);
    *(uint4*)(lo + boff + 16) = make_uint4(lw[4], lw[5], lw[6], lw[7]);
}

// ===========================================================================
// bf16 HMMA GEMM, 2 CTAs/SM, ldmatrix, DOUBLE-BUFFERED smem (1 sync/chunk).
// grid.z selects (A, W, bias, C) tuple -> QKV projections fused in 1 launch.
// ===========================================================================
#define GSTRIDE 80
#define GB_AH 0
#define GB_AL (128 * GSTRIDE)
#define GB_BH (2 * 128 * GSTRIDE)
#define GB_BL (3 * 128 * GSTRIDE)
#define GBUF_SZ (4 * 128 * GSTRIDE)     // 40960
#define GEMM_SMEM (2 * GBUF_SZ)         // 81920

__global__ __launch_bounds__(256, 2) void gemm_tc(
    const float* __restrict__ A0, const float* __restrict__ A1,
    const float* __restrict__ A2,
    const float* __restrict__ W0, const float* __restrict__ W1,
    const float* __restrict__ W2,
    const float* __restrict__ bs0, const float* __restrict__ bs1,
    const float* __restrict__ bs2,
    float* __restrict__ C0, float* __restrict__ C1, float* __restrict__ C2,
    int M, int N, int K)
{
    extern __shared__ char smc[];
    const uint32_t sbG = smem_u32(smc);

    const int z = blockIdx.z;
    const float* A    = (z == 0) ? A0 : (z == 1) ? A1 : A2;
    const float* Bw   = (z == 0) ? W0 : (z == 1) ? W1 : W2;
    const float* bias = (z == 0) ? bs0 : (z == 1) ? bs1 : bs2;
    float*       C    = (z == 0) ? C0 : (z == 1) ? C1 : C2;

    const int tid = threadIdx.x;
    const int wid = tid >> 5, lane = tid & 31;
    const int g = lane >> 2, t = lane & 3;
    const int warp_m = wid & 3;
    const int warp_n = wid >> 2;
    const int m0 = blockIdx.y * 128;
    const int n0 = blockIdx.x * 128;

    const int l7 = lane & 7;
    const int lh = (lane >> 3) & 1;
    const int lq = lane >> 4;
    const uint32_t aRel =
        (uint32_t)(warp_m * 32 + l7 + lh * 8) * GSTRIDE + (uint32_t)lq * 16;
    const uint32_t bRel =
        (uint32_t)(warp_n * 64 + l7) * GSTRIDE + (uint32_t)lh * 16;

    const int r = tid >> 1, h = tid & 1;
    const float* gA = A + (size_t)(m0 + r) * K + h * 16;
    const float* gB = Bw + (size_t)(n0 + r) * K + h * 16;
    const uint32_t boff = (uint32_t)r * GSTRIDE + h * 32;

    float acc[2][8][4];
#pragma unroll
    for (int mi = 0; mi < 2; mi++)
#pragma unroll
        for (int ni = 0; ni < 8; ni++)
#pragma unroll
            for (int c = 0; c < 4; c++) acc[mi][ni][c] = 0.f;

    const int nchunks = K / 32;

    // Prologue: chunk0 -> buf0; prefetch chunk1 into regs.
    float4 vA[4], vB[4];
#pragma unroll
    for (int q = 0; q < 4; q++) {
        vA[q] = *(const float4*)(gA + q * 4);
        vB[q] = *(const float4*)(gB + q * 4);
    }
    store_split16(vA, smc + GB_AH, smc + GB_AL, boff);
    store_split16(vB, smc + GB_BH, smc + GB_BL, boff);
#pragma unroll
    for (int q = 0; q < 4; q++) {
        vA[q] = *(const float4*)(gA + 32 + q * 4);
        vB[q] = *(const float4*)(gB + 32 + q * 4);
    }
    __syncthreads();

    for (int ck = 0; ck < nchunks; ck++) {
        const uint32_t bb = sbG + (uint32_t)(ck & 1) * GBUF_SZ;

        // MMA phase on buffer (ck & 1)
#pragma unroll
        for (int ks = 0; ks < 2; ks++) {
#pragma unroll
            for (int mi = 0; mi < 2; mi++) {
                uint32_t ah[4], al[4];
                LDSM_X4(ah, bb + GB_AH + aRel + mi * (16 * GSTRIDE) + ks * 32);
                LDSM_X4(al, bb + GB_AL + aRel + mi * (16 * GSTRIDE) + ks * 32);
#pragma unroll
                for (int ni = 0; ni < 8; ni++) {
                    uint32_t bh[2], bl[2];
                    LDSM_X2(bh, bb + GB_BH + bRel + ni * (8 * GSTRIDE) + ks * 32);
                    LDSM_X2(bl, bb + GB_BL + bRel + ni * (8 * GSTRIDE) + ks * 32);
                    MMA16816(acc[mi][ni], ah, bh);
                    MMA16816(acc[mi][ni], ah, bl);
                    MMA16816(acc[mi][ni], al, bh);
                }
            }
        }

        // Stage chunk ck+1 into the other buffer (overlaps other CTA's MMAs)
        if (ck + 1 < nchunks) {
            char* ob = smc + ((ck + 1) & 1) * GBUF_SZ;
            store_split16(vA, ob + GB_AH, ob + GB_AL, boff);
            store_split16(vB, ob + GB_BH, ob + GB_BL, boff);
        }
        // Prefetch chunk ck+2 (latency covered by next MMA phase)
        if (ck + 2 < nchunks) {
            const float* pa = gA + (ck + 2) * 32;
            const float* pb = gB + (ck + 2) * 32;
#pragma unroll
            for (int q = 0; q < 4; q++) {
                vA[q] = *(const float4*)(pa + q * 4);
                vB[q] = *(const float4*)(pb + q * 4);
            }
        }
        __syncthreads();
    }

#pragma unroll
    for (int mi = 0; mi < 2; mi++) {
        const int row0 = m0 + warp_m * 32 + mi * 16 + g;
#pragma unroll
        for (int ni = 0; ni < 8; ni++) {
            const int col = n0 + warp_n * 64 + ni * 8 + t * 2;
            float2 bi = *(const float2*)&bias[col];
            float2 o0, o1;
            o0.x = acc[mi][ni][0] + bi.x;
            o0.y = acc[mi][ni][1] + bi.y;
            o1.x = acc[mi][ni][2] + bi.x;
            o1.y = acc[mi][ni][3] + bi.y;
            *(float2*)&C[(size_t)row0 * N + col] = o0;
            *(float2*)&C[(size_t)(row0 + 8) * N + col] = o1;
        }
    }
}

// ===========================================================================
// Tensor-core flash attention, 2 CTAs/SM, ldmatrix, DOUBLE-BUFFERED K/V
// (1 sync/tile; LDG of next tile covered by PV phase).
// ===========================================================================
#define FSTB 144                       // bytes per smem row (72 bf16)
#define FQ_H 0
#define FQ_L (128 * FSTB)              // 18432
#define FB_KH 0
#define FB_KL (64 * FSTB)              // 9216
#define FB_VH (2 * 64 * FSTB)          // 18432
#define FB_VL (3 * 64 * FSTB)          // 27648
#define FBUF_SZ (4 * 64 * FSTB)        // 36864
#define FBUF0 (2 * 128 * FSTB)         // 36864
#define FLASH_SMEM (FBUF0 + 2 * FBUF_SZ)   // 110592

__global__ __launch_bounds__(256, 2) void flash_tc(
    const float* __restrict__ Q, const float* __restrict__ K,
    const float* __restrict__ V, const int* __restrict__ mask,
    float* __restrict__ ctx)
{
    extern __shared__ char smf[];
    const uint32_t sb = smem_u32(smf);
    const int tid = threadIdx.x;
    const int wid = tid >> 5, lane = tid & 31;
    const int g = lane >> 2, t = lane & 3;
    const int b = blockIdx.z, h = blockIdx.y;
    const int q0 = blockIdx.x * 128;

    const float* Qb = Q + ((size_t)b * S_ + q0) * D_ + h * DK_;
    const float* Kb = K + (size_t)b * S_ * D_ + h * DK_;
    const float* Vb = V + (size_t)b * S_ * D_ + h * DK_;
    const int*   Mb = mask + (size_t)b * S_ * S_;

    const int l7 = lane & 7;
    const int lh = (lane >> 3) & 1;
    const int lq = lane >> 4;
    const uint32_t qBase = sb +
        (uint32_t)(wid * 16 + l7 + lh * 8) * FSTB + (uint32_t)lq * 16;
    const uint32_t kRel = (uint32_t)l7 * FSTB + (uint32_t)lh * 16;
    const uint32_t vRel = (uint32_t)(l7 + lh * 8) * FSTB;

    // K/V staging assignment
    const int kr = tid >> 2;
    const int cs = (tid & 3) * 16;
    const uint32_t stoff = (uint32_t)kr * FSTB + cs * 2;

    // ---- Stage Q once: scale 0.125, split hi/lo ----
    {
        const int r = tid >> 1, hf = tid & 1;
        const float* src = Qb + (size_t)r * D_ + hf * 32;
#pragma unroll
        for (int seg = 0; seg < 2; seg++) {
            float4 v[4];
#pragma unroll
            for (int j = 0; j < 4; j++) {
                float4 x = *(const float4*)(src + seg * 16 + j * 4);
                x.x *= 0.125f; x.y *= 0.125f; x.z *= 0.125f; x.w *= 0.125f;
                v[j] = x;
            }
            store_split16(v, smf + FQ_H, smf + FQ_L,
                          (uint32_t)r * FSTB + hf * 64 + seg * 32);
        }
    }

    // ---- Prologue: stage K/V tile 0 into buf0 ----
    {
        float4 vK[4], vV[4];
        const float* srcK = Kb + (size_t)kr * D_ + cs;
        const float* srcV = Vb + (size_t)kr * D_ + cs;
#pragma unroll
        for (int j = 0; j < 4; j++) {
            vK[j] = *(const float4*)(srcK + j * 4);
            vV[j] = *(const float4*)(srcV + j * 4);
        }
        char* bufc = smf + FBUF0;
        store_split16(vK, bufc + FB_KH, bufc + FB_KL, stoff);
        store_split16(vV, bufc + FB_VH, bufc + FB_VL, stoff);
    }
    __syncthreads();

    float O[8][4];
#pragma unroll
    for (int ni = 0; ni < 8; ni++)
#pragma unroll
        for (int c = 0; c < 4; c++) O[ni][c] = 0.f;

    float m0r = -3.0e38f, m1r = -3.0e38f;
    float l0r = 0.f, l1r = 0.f;

    const int r0g = q0 + wid * 16 + g;
    const int r1g = r0g + 8;

    const int NT = S_ / 64;   // 32 tiles
    for (int it = 0; it < NT; it++) {
        const uint32_t bb = sb + FBUF0 + (uint32_t)(it & 1) * FBUF_SZ;

        // ---- S = (Q*0.125) @ K^T : 3-term split, ldmatrix frags ----
        float s[8][4];
#pragma unroll
        for (int ni = 0; ni < 8; ni++)
#pragma unroll
            for (int c = 0; c < 4; c++) s[ni][c] = 0.f;

#pragma unroll
        for (int ks = 0; ks < 4; ks++) {
            uint32_t qh[4], ql[4];
            LDSM_X4(qh, qBase + FQ_H + ks * 32);
            LDSM_X4(ql, qBase + FQ_L + ks * 32);
#pragma unroll
            for (int ni = 0; ni < 8; ni++) {
                uint32_t kh[2], kl[2];
                LDSM_X2(kh, bb + FB_KH + kRel + ni * (8 * FSTB) + ks * 32);
                LDSM_X2(kl, bb + FB_KL + kRel + ni * (8 * FSTB) + ks * 32);
                MMA16816(s[ni], qh, kh);
                MMA16816(s[ni], qh, kl);
                MMA16816(s[ni], ql, kh);
            }
        }

        // ---- Mask ----
        const int kt = it * 64;
#pragma unroll
        for (int ni = 0; ni < 8; ni++) {
            const int c = kt + ni * 8 + t * 2;
            int2 mk0 = *(const int2*)(Mb + (size_t)r0g * S_ + c);
            int2 mk1 = *(const int2*)(Mb + (size_t)r1g * S_ + c);
            if (!mk0.x) s[ni][0] = NEGV;
            if (!mk0.y) s[ni][1] = NEGV;
            if (!mk1.x) s[ni][2] = NEGV;
            if (!mk1.y) s[ni][3] = NEGV;
        }

        // ---- Online softmax (within t-quad) ----
        float mx0 = s[0][0], mx1 = s[0][2];
#pragma unroll
        for (int ni = 0; ni < 8; ni++) {
            mx0 = fmaxf(mx0, fmaxf(s[ni][0], s[ni][1]));
            mx1 = fmaxf(mx1, fmaxf(s[ni][2], s[ni][3]));
        }
        mx0 = fmaxf(mx0, __shfl_xor_sync(0xffffffffu, mx0, 1));
        mx0 = fmaxf(mx0, __shfl_xor_sync(0xffffffffu, mx0, 2));
        mx1 = fmaxf(mx1, __shfl_xor_sync(0xffffffffu, mx1, 1));
        mx1 = fmaxf(mx1, __shfl_xor_sync(0xffffffffu, mx1, 2));

        const float mn0 = fmaxf(m0r, mx0);
        const float mn1 = fmaxf(m1r, mx1);
        const float a0 = __expf(m0r - mn0);
        const float a1 = __expf(m1r - mn1);
        m0r = mn0; m1r = mn1;

        float sum0 = 0.f, sum1 = 0.f;
#pragma unroll
        for (int ni = 0; ni < 8; ni++) {
            s[ni][0] = __expf(s[ni][0] - mn0);
            s[ni][1] = __expf(s[ni][1] - mn0);
            s[ni][2] = __expf(s[ni][2] - mn1);
            s[ni][3] = __expf(s[ni][3] - mn1);
            sum0 += s[ni][0] + s[ni][1];
            sum1 += s[ni][2] + s[ni][3];
        }
        sum0 += __shfl_xor_sync(0xffffffffu, sum0, 1);
        sum0 += __shfl_xor_sync(0xffffffffu, sum0, 2);
        sum1 += __shfl_xor_sync(0xffffffffu, sum1, 1);
        sum1 += __shfl_xor_sync(0xffffffffu, sum1, 2);
        l0r = l0r * a0 + sum0;
        l1r = l1r * a1 + sum1;

#pragma unroll
        for (int ni = 0; ni < 8; ni++) {
            O[ni][0] *= a0; O[ni][1] *= a0;
            O[ni][2] *= a1; O[ni][3] *= a1;
        }

        // ---- Prefetch next K/V tile (latency covered by PV phase) ----
        float4 vK[4], vV[4];
        if (it + 1 < NT) {
            const float* srcK = Kb + (size_t)(kt + 64 + kr) * D_ + cs;
            const float* srcV = Vb + (size_t)(kt + 64 + kr) * D_ + cs;
#pragma unroll
            for (int j = 0; j < 4; j++) {
                vK[j] = *(const float4*)(srcK + j * 4);
                vV[j] = *(const float4*)(srcV + j * 4);
            }
        }

        // ---- PV: O += P @ V (P from regs; V frags via ldmatrix.trans) ----
#pragma unroll
        for (int ksp = 0; ksp < 4; ksp++) {
            uint32_t pah[4], pal[4];
#pragma unroll
            for (int hf = 0; hf < 2; hf++) {
                const float* p = s[2 * ksp + hf];
                __nv_bfloat162 h01 = __floats2bfloat162_rn(p[0], p[1]);
                __nv_bfloat162 h23 = __floats2bfloat162_rn(p[2], p[3]);
                float2 f01 = __bfloat1622float2(h01);
                float2 f23 = __bfloat1622float2(h23);
                __nv_bfloat162 l01 =
                    __floats2bfloat162_rn(p[0] - f01.x, p[1] - f01.y);
                __nv_bfloat162 l23 =
                    __floats2bfloat162_rn(p[2] - f23.x, p[3] - f23.y);
                pah[hf * 2 + 0] = *(const uint32_t*)&h01;
                pah[hf * 2 + 1] = *(const uint32_t*)&h23;
                pal[hf * 2 + 0] = *(const uint32_t*)&l01;
                pal[hf * 2 + 1] = *(const uint32_t*)&l23;
            }
#pragma unroll
            for (int ni = 0; ni < 8; ni++) {
                uint32_t vh[2], vl[2];
                LDSM_X2T(vh, bb + FB_VH + vRel + ksp * (16 * FSTB) + ni * 16);
                LDSM_X2T(vl, bb + FB_VL + vRel + ksp * (16 * FSTB) + ni * 16);
                MMA16816(O[ni], pah, vh);
                MMA16816(O[ni], pah, vl);
                MMA16816(O[ni], pal, vh);
            }
        }

        // ---- Stage next tile into the other buffer ----
        if (it + 1 < NT) {
            char* ob = smf + FBUF0 + ((it + 1) & 1) * FBUF_SZ;
            store_split16(vK, ob + FB_KH, ob + FB_KL, stoff);
            store_split16(vV, ob + FB_VH, ob + FB_VL, stoff);
        }
        __syncthreads();
    }

    // ---- Final normalize + store ----
    const float ri0 = 1.f / l0r;
    const float ri1 = 1.f / l1r;
    float* C0 = ctx + ((size_t)b * S_ + r0g) * D_ + h * DK_;
    float* C1 = ctx + ((size_t)b * S_ + r1g) * D_ + h * DK_;
#pragma unroll
    for (int ni = 0; ni < 8; ni++) {
        const int c = ni * 8 + t * 2;
        float2 o0, o1;
        o0.x = O[ni][0] * ri0; o0.y = O[ni][1] * ri0;
        o1.x = O[ni][2] * ri1; o1.y = O[ni][3] * ri1;
        *(float2*)(C0 + c) = o0;
        *(float2*)(C1 + c) = o1;
    }
}

// ---------------------------------------------------------------------------
// Launch
// ---------------------------------------------------------------------------
extern "C" void kernel_launch(void* const* d_in, const int* in_sizes, int n_in,
                              void* d_out, int out_size)
{
    const float* query = (const float*)d_in[0];
    const float* key   = (const float*)d_in[1];
    const float* value = (const float*)d_in[2];
    const int*   mask  = (const int*)d_in[3];
    const float* w_q = (const float*)d_in[4];
    const float* b_q = (const float*)d_in[5];
    const float* w_k = (const float*)d_in[6];
    const float* b_k = (const float*)d_in[7];
    const float* w_v = (const float*)d_in[8];
    const float* b_v = (const float*)d_in[9];
    const float* w_o = (const float*)d_in[10];
    const float* b_o = (const float*)d_in[11];

    float *gq, *gk, *gv, *gc;
    cudaGetSymbolAddress((void**)&gq, g_q);
    cudaGetSymbolAddress((void**)&gk, g_k);
    cudaGetSymbolAddress((void**)&gv, g_v);
    cudaGetSymbolAddress((void**)&gc, g_ctx);

    cudaFuncSetAttribute(gemm_tc,
                         cudaFuncAttributeMaxDynamicSharedMemorySize,
                         GEMM_SMEM);
    cudaFuncSetAttribute(flash_tc,
                         cudaFuncAttributeMaxDynamicSharedMemorySize,
                         FLASH_SMEM);

    const int M = B_ * S_;                        // 4096

    // Fused QKV projections: grid.z selects (A, W, bias, C)
    dim3 gqkv(D_ / 128, M / 128, 3);              // (8, 32, 3) = 768 CTAs
    gemm_tc<<<gqkv, 256, GEMM_SMEM>>>(
        query, key, value,
        w_q, w_k, w_v,
        b_q, b_k, b_v,
        gq, gk, gv,
        M, D_, D_);

    dim3 gflash(S_ / 128, H_, B_);                // (16, 16, 2) = 512 CTAs
    flash_tc<<<gflash, 256, FLASH_SMEM>>>(gq, gk, gv, mask, gc);

    // Output projection (single tuple in slot 0)
    dim3 gproj(D_ / 128, M / 128, 1);
    gemm_tc<<<gproj, 256, GEMM_SMEM>>>(
        gc, gc, gc,
        w_o, w_o, w_o,
        b_o, b_o, b_o,
        (float*)d_out, (float*)d_out, (float*)d_out,
        M, D_, D_);
}

// round 14
// speedup vs baseline: 1.1219x; 1.1219x over previous
#include <cuda_runtime.h>
#include <cuda_bf16.h>
#include <cstdint>

#define B_  2
#define S_  2048
#define D_  1024
#define H_  16
#define DK_ 64
#define NEGV -1.0e9f

// Scratch (allocation-free rule: __device__ globals)
// Pre-split bf16 hi/lo images of q(*0.125), k, v written by projection epilogue.
__device__ __nv_bfloat16 g_qh[B_ * S_ * D_];
__device__ __nv_bfloat16 g_ql[B_ * S_ * D_];
__device__ __nv_bfloat16 g_kh[B_ * S_ * D_];
__device__ __nv_bfloat16 g_kl[B_ * S_ * D_];
__device__ __nv_bfloat16 g_vh[B_ * S_ * D_];
__device__ __nv_bfloat16 g_vl[B_ * S_ * D_];
__device__ float g_ctx[B_ * S_ * D_];

// ===========================================================================
// Common helpers
// ===========================================================================
#define MMA16816(c, a, b) \
    asm volatile("mma.sync.aligned.m16n8k16.row.col.f32.bf16.bf16.f32 " \
        "{%0,%1,%2,%3}, {%4,%5,%6,%7}, {%8,%9}, {%0,%1,%2,%3};" \
        : "+f"((c)[0]), "+f"((c)[1]), "+f"((c)[2]), "+f"((c)[3]) \
        : "r"((a)[0]), "r"((a)[1]), "r"((a)[2]), "r"((a)[3]), \
          "r"((b)[0]), "r"((b)[1]))

#define LDSM_X4(d, addr) \
    asm volatile("ldmatrix.sync.aligned.m8n8.x4.shared.b16 {%0,%1,%2,%3}, [%4];" \
        : "=r"((d)[0]), "=r"((d)[1]), "=r"((d)[2]), "=r"((d)[3]) : "r"(addr))

#define LDSM_X2(d, addr) \
    asm volatile("ldmatrix.sync.aligned.m8n8.x2.shared.b16 {%0,%1}, [%2];" \
        : "=r"((d)[0]), "=r"((d)[1]) : "r"(addr))

#define LDSM_X2T(d, addr) \
    asm volatile("ldmatrix.sync.aligned.m8n8.x2.trans.shared.b16 {%0,%1}, [%2];" \
        : "=r"((d)[0]), "=r"((d)[1]) : "r"(addr))

#define CP16(dst, src) \
    asm volatile("cp.async.ca.shared.global [%0], [%1], 16;" \
        :: "r"(dst), "l"(src) : "memory")
#define CP_COMMIT() asm volatile("cp.async.commit_group;" ::: "memory")
#define CP_WAIT0()  asm volatile("cp.async.wait_group 0;" ::: "memory")

__device__ __forceinline__ uint32_t smem_u32(const void* p) {
    uint32_t a;
    asm("{ .reg .u64 t; cvta.to.shared.u64 t, %1; cvt.u32.u64 %0, t; }"
        : "=r"(a) : "l"(p));
    return a;
}

// Convert 16 fp32 (4 float4) -> 16 bf16 hi + 16 bf16 lo via cvt.rn.bf16x2.
__device__ __forceinline__ void store_split16(
    const float4* v, char* hi, char* lo, uint32_t boff)
{
    uint32_t hw[8], lw[8];
#pragma unroll
    for (int q = 0; q < 4; q++) {
        __nv_bfloat162 h0 = __floats2bfloat162_rn(v[q].x, v[q].y);
        __nv_bfloat162 h1 = __floats2bfloat162_rn(v[q].z, v[q].w);
        float2 f0 = __bfloat1622float2(h0);
        float2 f1 = __bfloat1622float2(h1);
        __nv_bfloat162 l0 = __floats2bfloat162_rn(v[q].x - f0.x, v[q].y - f0.y);
        __nv_bfloat162 l1 = __floats2bfloat162_rn(v[q].z - f1.x, v[q].w - f1.y);
        hw[q * 2]     = *(const uint32_t*)&h0;
        hw[q * 2 + 1] = *(const uint32_t*)&h1;
        lw[q * 2]     = *(const uint32_t*)&l0;
        lw[q * 2 + 1] = *(const uint32_t*)&l1;
    }
    *(uint4*)(hi + boff)      = make_uint4(hw[0], hw[1], hw[2], hw[3]);
    *(uint4*)(hi + boff + 16) = make_uint4(hw[4], hw[5], hw[6], hw[7]);
    *(uint4*)(lo + boff)      = make_uint4(lw[0], lw[1], lw[2], lw[3]);
    *(uint4*)(lo + boff + 16) = make_uint4(lw[4], lw[5], lw[6], lw[7]);
}

// ===========================================================================
// GEMM mainloop (shared by both epilogues).
// CTA 128x128, warp grid 2(m) x 4(n), warp tile 64x32.
// B-frags hoisted across mi -> B-frag smem traffic cut 4x.
// Double-buffered smem, 1 sync/chunk; LDG of ck+1 issued mid-MMA (ks0/ks1).
// ===========================================================================
#define GSTRIDE 80
#define GB_AH 0
#define GB_AL (128 * GSTRIDE)
#define GB_BH (2 * 128 * GSTRIDE)
#define GB_BL (3 * 128 * GSTRIDE)
#define GBUF_SZ (4 * 128 * GSTRIDE)     // 40960
#define GEMM_SMEM (2 * GBUF_SZ)         // 81920

__device__ __forceinline__ void gemm_mainloop(
    const float* __restrict__ A, const float* __restrict__ Bw,
    int K, char* smc, int m0, int n0, float acc[4][4][4])
{
    const uint32_t sbG = smem_u32(smc);
    const int tid = threadIdx.x;
    const int wid = tid >> 5, lane = tid & 31;
    const int warp_m = wid & 1;     // 2 groups of 64 rows
    const int warp_n = wid >> 1;    // 4 groups of 32 cols

    const int l7 = lane & 7;
    const int lh = (lane >> 3) & 1;
    const int lq = lane >> 4;
    const uint32_t aRel =
        (uint32_t)(warp_m * 64 + l7 + lh * 8) * GSTRIDE + (uint32_t)lq * 16;
    const uint32_t bRel =
        (uint32_t)(warp_n * 32 + l7) * GSTRIDE + (uint32_t)lh * 16;

    const int r = tid >> 1, h = tid & 1;
    const float* gA = A + (size_t)(m0 + r) * K + h * 16;
    const float* gB = Bw + (size_t)(n0 + r) * K + h * 16;
    const uint32_t boff = (uint32_t)r * GSTRIDE + h * 32;

#pragma unroll
    for (int mi = 0; mi < 4; mi++)
#pragma unroll
        for (int ni = 0; ni < 4; ni++)
#pragma unroll
            for (int c = 0; c < 4; c++) acc[mi][ni][c] = 0.f;

    const int nchunks = K / 32;

    // Prologue: stage chunk 0 into buf0.
    {
        float4 vA[4], vB[4];
#pragma unroll
        for (int q = 0; q < 4; q++) {
            vA[q] = *(const float4*)(gA + q * 4);
            vB[q] = *(const float4*)(gB + q * 4);
        }
        store_split16(vA, smc + GB_AH, smc + GB_AL, boff);
        store_split16(vB, smc + GB_BH, smc + GB_BL, boff);
    }
    __syncthreads();

    for (int ck = 0; ck < nchunks; ck++) {
        const uint32_t bb = sbG + (uint32_t)(ck & 1) * GBUF_SZ;
        float4 vA[4], vB[4];

        // ---- ks = 0 ----
        {
            uint32_t bh[4][2], bl[4][2];
#pragma unroll
            for (int ni = 0; ni < 4; ni++) {
                LDSM_X2(bh[ni], bb + GB_BH + bRel + ni * (8 * GSTRIDE));
                LDSM_X2(bl[ni], bb + GB_BL + bRel + ni * (8 * GSTRIDE));
            }
#pragma unroll
            for (int mi = 0; mi < 4; mi++) {
                uint32_t ah[4], al[4];
                LDSM_X4(ah, bb + GB_AH + aRel + mi * (16 * GSTRIDE));
                LDSM_X4(al, bb + GB_AL + aRel + mi * (16 * GSTRIDE));
#pragma unroll
                for (int ni = 0; ni < 4; ni++) {
                    MMA16816(acc[mi][ni], ah, bh[ni]);
                    MMA16816(acc[mi][ni], ah, bl[ni]);
                    MMA16816(acc[mi][ni], al, bh[ni]);
                }
            }
        }

        // LDG of next chunk, latency covered by ks=1 MMA phase.
        if (ck + 1 < nchunks) {
            const float* pa = gA + (ck + 1) * 32;
            const float* pb = gB + (ck + 1) * 32;
#pragma unroll
            for (int q = 0; q < 4; q++) {
                vA[q] = *(const float4*)(pa + q * 4);
                vB[q] = *(const float4*)(pb + q * 4);
            }
        }

        // ---- ks = 1 ----
        {
            uint32_t bh[4][2], bl[4][2];
#pragma unroll
            for (int ni = 0; ni < 4; ni++) {
                LDSM_X2(bh[ni], bb + GB_BH + bRel + ni * (8 * GSTRIDE) + 32);
                LDSM_X2(bl[ni], bb + GB_BL + bRel + ni * (8 * GSTRIDE) + 32);
            }
#pragma unroll
            for (int mi = 0; mi < 4; mi++) {
                uint32_t ah[4], al[4];
                LDSM_X4(ah, bb + GB_AH + aRel + mi * (16 * GSTRIDE) + 32);
                LDSM_X4(al, bb + GB_AL + aRel + mi * (16 * GSTRIDE) + 32);
#pragma unroll
                for (int ni = 0; ni < 4; ni++) {
                    MMA16816(acc[mi][ni], ah, bh[ni]);
                    MMA16816(acc[mi][ni], ah, bl[ni]);
                    MMA16816(acc[mi][ni], al, bh[ni]);
                }
            }
        }

        // Stage next chunk into the other buffer.
        if (ck + 1 < nchunks) {
            char* ob = smc + ((ck + 1) & 1) * GBUF_SZ;
            store_split16(vA, ob + GB_AH, ob + GB_AL, boff);
            store_split16(vB, ob + GB_BH, ob + GB_BL, boff);
        }
        __syncthreads();
    }
}

// ---- QKV projection: epilogue writes pre-split bf16 hi/lo (+scale) ----
__global__ __launch_bounds__(256, 2) void gemm_split(
    const float* __restrict__ A0, const float* __restrict__ A1,
    const float* __restrict__ A2,
    const float* __restrict__ W0, const float* __restrict__ W1,
    const float* __restrict__ W2,
    const float* __restrict__ bs0, const float* __restrict__ bs1,
    const float* __restrict__ bs2,
    __nv_bfloat16* __restrict__ H0, __nv_bfloat16* __restrict__ H1,
    __nv_bfloat16* __restrict__ H2,
    __nv_bfloat16* __restrict__ L0, __nv_bfloat16* __restrict__ L1,
    __nv_bfloat16* __restrict__ L2,
    int M, int N, int K)
{
    extern __shared__ char smc[];
    const int z = blockIdx.z;
    const float* A    = (z == 0) ? A0 : (z == 1) ? A1 : A2;
    const float* Bw   = (z == 0) ? W0 : (z == 1) ? W1 : W2;
    const float* bias = (z == 0) ? bs0 : (z == 1) ? bs1 : bs2;
    __nv_bfloat16* Ch = (z == 0) ? H0 : (z == 1) ? H1 : H2;
    __nv_bfloat16* Cl = (z == 0) ? L0 : (z == 1) ? L1 : L2;
    const float scale = (z == 0) ? 0.125f : 1.0f;

    const int m0 = blockIdx.y * 128;
    const int n0 = blockIdx.x * 128;
    float acc[4][4][4];
    gemm_mainloop(A, Bw, K, smc, m0, n0, acc);

    const int wid = threadIdx.x >> 5, lane = threadIdx.x & 31;
    const int g = lane >> 2, t = lane & 3;
    const int warp_m = wid & 1, warp_n = wid >> 1;

#pragma unroll
    for (int mi = 0; mi < 4; mi++) {
        const int row0 = m0 + warp_m * 64 + mi * 16 + g;
#pragma unroll
        for (int ni = 0; ni < 4; ni++) {
            const int col = n0 + warp_n * 32 + ni * 8 + t * 2;
            float2 bi = *(const float2*)&bias[col];
            float c0 = (acc[mi][ni][0] + bi.x) * scale;
            float c1 = (acc[mi][ni][1] + bi.y) * scale;
            float c2 = (acc[mi][ni][2] + bi.x) * scale;
            float c3 = (acc[mi][ni][3] + bi.y) * scale;
            __nv_bfloat162 h01 = __floats2bfloat162_rn(c0, c1);
            __nv_bfloat162 h23 = __floats2bfloat162_rn(c2, c3);
            float2 f01 = __bfloat1622float2(h01);
            float2 f23 = __bfloat1622float2(h23);
            __nv_bfloat162 l01 = __floats2bfloat162_rn(c0 - f01.x, c1 - f01.y);
            __nv_bfloat162 l23 = __floats2bfloat162_rn(c2 - f23.x, c3 - f23.y);
            *(__nv_bfloat162*)&Ch[(size_t)row0 * N + col] = h01;
            *(__nv_bfloat162*)&Ch[(size_t)(row0 + 8) * N + col] = h23;
            *(__nv_bfloat162*)&Cl[(size_t)row0 * N + col] = l01;
            *(__nv_bfloat162*)&Cl[(size_t)(row0 + 8) * N + col] = l23;
        }
    }
}

// ---- Output projection: fp32 epilogue ----
__global__ __launch_bounds__(256, 2) void gemm_f32(
    const float* __restrict__ A, const float* __restrict__ Bw,
    const float* __restrict__ bias, float* __restrict__ C,
    int M, int N, int K)
{
    extern __shared__ char smc[];
    const int m0 = blockIdx.y * 128;
    const int n0 = blockIdx.x * 128;
    float acc[4][4][4];
    gemm_mainloop(A, Bw, K, smc, m0, n0, acc);

    const int wid = threadIdx.x >> 5, lane = threadIdx.x & 31;
    const int g = lane >> 2, t = lane & 3;
    const int warp_m = wid & 1, warp_n = wid >> 1;

#pragma unroll
    for (int mi = 0; mi < 4; mi++) {
        const int row0 = m0 + warp_m * 64 + mi * 16 + g;
#pragma unroll
        for (int ni = 0; ni < 4; ni++) {
            const int col = n0 + warp_n * 32 + ni * 8 + t * 2;
            float2 bi = *(const float2*)&bias[col];
            float2 o0, o1;
            o0.x = acc[mi][ni][0] + bi.x;
            o0.y = acc[mi][ni][1] + bi.y;
            o1.x = acc[mi][ni][2] + bi.x;
            o1.y = acc[mi][ni][3] + bi.y;
            *(float2*)&C[(size_t)row0 * N + col] = o0;
            *(float2*)&C[(size_t)(row0 + 8) * N + col] = o1;
        }
    }
}

// ===========================================================================
// Tensor-core flash attention, 2 CTAs/SM.
// Inputs are pre-split bf16 hi/lo (q pre-scaled). Staging via cp.async —
// no conversion, no register round trip. Q-frags hoisted whole-kernel.
// ===========================================================================
#define FSTB 144                       // bytes per smem row (72 bf16)
#define FQ_H 0
#define FQ_L (128 * FSTB)              // 18432
#define FB_KH 0
#define FB_KL (64 * FSTB)              // 9216
#define FB_VH (2 * 64 * FSTB)          // 18432
#define FB_VL (3 * 64 * FSTB)          // 27648
#define FBUF_SZ (4 * 64 * FSTB)        // 36864
#define FBUF0 (2 * 128 * FSTB)         // 36864
#define FLASH_SMEM (FBUF0 + 2 * FBUF_SZ)   // 110592

__global__ __launch_bounds__(256, 2) void flash_tc(
    const __nv_bfloat16* __restrict__ QH, const __nv_bfloat16* __restrict__ QL,
    const __nv_bfloat16* __restrict__ KH, const __nv_bfloat16* __restrict__ KL,
    const __nv_bfloat16* __restrict__ VH, const __nv_bfloat16* __restrict__ VL,
    const int* __restrict__ mask, float* __restrict__ ctx)
{
    extern __shared__ char smf[];
    const uint32_t sb = smem_u32(smf);
    const int tid = threadIdx.x;
    const int wid = tid >> 5, lane = tid & 31;
    const int g = lane >> 2, t = lane & 3;
    const int b = blockIdx.z, h = blockIdx.y;
    const int q0 = blockIdx.x * 128;

    const size_t bS = (size_t)b * S_;
    const int* Mb = mask + bS * S_;

    const int l7 = lane & 7;
    const int lh = (lane >> 3) & 1;
    const int lq = lane >> 4;
    const uint32_t qBase = sb +
        (uint32_t)(wid * 16 + l7 + lh * 8) * FSTB + (uint32_t)lq * 16;
    const uint32_t kRel = (uint32_t)l7 * FSTB + (uint32_t)lh * 16;
    const uint32_t vRel = (uint32_t)(l7 + lh * 8) * FSTB;

    // K/V cp.async assignment: row kr, 32B chunk cc
    const int kr = tid >> 2;
    const uint32_t cc = (uint32_t)(tid & 3) * 32;
    const size_t kvElemBase = (bS + kr) * D_ + h * DK_;

    // ---- Prologue: cp.async Q (whole) + K/V tile 0 ----
    {
        const int qr = tid >> 1;
        const uint32_t qcc = (uint32_t)(tid & 1) * 64;
        const char* srcQH = (const char*)(QH + (bS + q0 + qr) * D_ + h * DK_) + qcc;
        const char* srcQL = (const char*)(QL + (bS + q0 + qr) * D_ + h * DK_) + qcc;
        const uint32_t dq = sb + (uint32_t)qr * FSTB + qcc;
#pragma unroll
        for (int j = 0; j < 4; j++) {
            CP16(dq + FQ_H + j * 16, srcQH + j * 16);
            CP16(dq + FQ_L + j * 16, srcQL + j * 16);
        }
        const uint32_t d0 = sb + FBUF0 + (uint32_t)kr * FSTB + cc;
        const char* sKH = (const char*)(KH + kvElemBase) + cc;
        const char* sKL = (const char*)(KL + kvElemBase) + cc;
        const char* sVH = (const char*)(VH + kvElemBase) + cc;
        const char* sVL = (const char*)(VL + kvElemBase) + cc;
        CP16(d0 + FB_KH, sKH);       CP16(d0 + FB_KH + 16, sKH + 16);
        CP16(d0 + FB_KL, sKL);       CP16(d0 + FB_KL + 16, sKL + 16);
        CP16(d0 + FB_VH, sVH);       CP16(d0 + FB_VH + 16, sVH + 16);
        CP16(d0 + FB_VL, sVL);       CP16(d0 + FB_VL + 16, sVL + 16);
        CP_COMMIT();
        CP_WAIT0();
    }
    __syncthreads();

    // ---- Hoist Q hi+lo fragments for the whole kernel ----
    uint32_t qh[4][4], ql[4][4];
#pragma unroll
    for (int ks = 0; ks < 4; ks++) {
        LDSM_X4(qh[ks], qBase + FQ_H + ks * 32);
        LDSM_X4(ql[ks], qBase + FQ_L + ks * 32);
    }

    float O[8][4];
#pragma unroll
    for (int ni = 0; ni < 8; ni++)
#pragma unroll
        for (int c = 0; c < 4; c++) O[ni][c] = 0.f;

    float m0r = -3.0e38f, m1r = -3.0e38f;
    float l0r = 0.f, l1r = 0.f;

    const int r0g = q0 + wid * 16 + g;
    const int r1g = r0g + 8;

    const int NT = S_ / 64;   // 32 tiles
    for (int it = 0; it < NT; it++) {
        const uint32_t bb = sb + FBUF0 + (uint32_t)(it & 1) * FBUF_SZ;
        const int kt = it * 64;

        // ---- S = Qs @ K^T (3-term split) ----
        float s[8][4];
#pragma unroll
        for (int ni = 0; ni < 8; ni++)
#pragma unroll
            for (int c = 0; c < 4; c++) s[ni][c] = 0.f;

#pragma unroll
        for (int ks = 0; ks < 4; ks++) {
#pragma unroll
            for (int ni = 0; ni < 8; ni++) {
                uint32_t kh[2], kl[2];
                LDSM_X2(kh, bb + FB_KH + kRel + ni * (8 * FSTB) + ks * 32);
                LDSM_X2(kl, bb + FB_KL + kRel + ni * (8 * FSTB) + ks * 32);
                MMA16816(s[ni], qh[ks], kh);
                MMA16816(s[ni], qh[ks], kl);
                MMA16816(s[ni], ql[ks], kh);
            }
        }

        // ---- Mask ----
#pragma unroll
        for (int ni = 0; ni < 8; ni++) {
            const int c = kt + ni * 8 + t * 2;
            int2 mk0 = *(const int2*)(Mb + (size_t)r0g * S_ + c);
            int2 mk1 = *(const int2*)(Mb + (size_t)r1g * S_ + c);
            if (!mk0.x) s[ni][0] = NEGV;
            if (!mk0.y) s[ni][1] = NEGV;
            if (!mk1.x) s[ni][2] = NEGV;
            if (!mk1.y) s[ni][3] = NEGV;
        }

        // ---- Online softmax (within t-quad) ----
        float mx0 = s[0][0], mx1 = s[0][2];
#pragma unroll
        for (int ni = 0; ni < 8; ni++) {
            mx0 = fmaxf(mx0, fmaxf(s[ni][0], s[ni][1]));
            mx1 = fmaxf(mx1, fmaxf(s[ni][2], s[ni][3]));
        }
        mx0 = fmaxf(mx0, __shfl_xor_sync(0xffffffffu, mx0, 1));
        mx0 = fmaxf(mx0, __shfl_xor_sync(0xffffffffu, mx0, 2));
        mx1 = fmaxf(mx1, __shfl_xor_sync(0xffffffffu, mx1, 1));
        mx1 = fmaxf(mx1, __shfl_xor_sync(0xffffffffu, mx1, 2));

        const float mn0 = fmaxf(m0r, mx0);
        const float mn1 = fmaxf(m1r, mx1);
        const float a0 = __expf(m0r - mn0);
        const float a1 = __expf(m1r - mn1);
        m0r = mn0; m1r = mn1;

        float sum0 = 0.f, sum1 = 0.f;
#pragma unroll
        for (int ni = 0; ni < 8; ni++) {
            s[ni][0] = __expf(s[ni][0] - mn0);
            s[ni][1] = __expf(s[ni][1] - mn0);
            s[ni][2] = __expf(s[ni][2] - mn1);
            s[ni][3] = __expf(s[ni][3] - mn1);
            sum0 += s[ni][0] + s[ni][1];
            sum1 += s[ni][2] + s[ni][3];
        }
        sum0 += __shfl_xor_sync(0xffffffffu, sum0, 1);
        sum0 += __shfl_xor_sync(0xffffffffu, sum0, 2);
        sum1 += __shfl_xor_sync(0xffffffffu, sum1, 1);
        sum1 += __shfl_xor_sync(0xffffffffu, sum1, 2);
        l0r = l0r * a0 + sum0;
        l1r = l1r * a1 + sum1;

#pragma unroll
        for (int ni = 0; ni < 8; ni++) {
            O[ni][0] *= a0; O[ni][1] *= a0;
            O[ni][2] *= a1; O[ni][3] *= a1;
        }

        // ---- Issue cp.async for next tile into other buffer ----
        if (it + 1 < NT) {
            const size_t nb = kvElemBase + (size_t)(kt + 64) * D_;
            const uint32_t dn = sb + FBUF0 + (uint32_t)((it + 1) & 1) * FBUF_SZ
                              + (uint32_t)kr * FSTB + cc;
            const char* sKH = (const char*)(KH + nb) + cc;
            const char* sKL = (const char*)(KL + nb) + cc;
            const char* sVH = (const char*)(VH + nb) + cc;
            const char* sVL = (const char*)(VL + nb) + cc;
            CP16(dn + FB_KH, sKH);    CP16(dn + FB_KH + 16, sKH + 16);
            CP16(dn + FB_KL, sKL);    CP16(dn + FB_KL + 16, sKL + 16);
            CP16(dn + FB_VH, sVH);    CP16(dn + FB_VH + 16, sVH + 16);
            CP16(dn + FB_VL, sVL);    CP16(dn + FB_VL + 16, sVL + 16);
            CP_COMMIT();
        }

        // ---- PV: O += P @ V (P from regs; V frags via ldmatrix.trans) ----
#pragma unroll
        for (int ksp = 0; ksp < 4; ksp++) {
            uint32_t pah[4], pal[4];
#pragma unroll
            for (int hf = 0; hf < 2; hf++) {
                const float* p = s[2 * ksp + hf];
                __nv_bfloat162 h01 = __floats2bfloat162_rn(p[0], p[1]);
                __nv_bfloat162 h23 = __floats2bfloat162_rn(p[2], p[3]);
                float2 f01 = __bfloat1622float2(h01);
                float2 f23 = __bfloat1622float2(h23);
                __nv_bfloat162 l01 =
                    __floats2bfloat162_rn(p[0] - f01.x, p[1] - f01.y);
                __nv_bfloat162 l23 =
                    __floats2bfloat162_rn(p[2] - f23.x, p[3] - f23.y);
                pah[hf * 2 + 0] = *(const uint32_t*)&h01;
                pah[hf * 2 + 1] = *(const uint32_t*)&h23;
                pal[hf * 2 + 0] = *(const uint32_t*)&l01;
                pal[hf * 2 + 1] = *(const uint32_t*)&l23;
            }
#pragma unroll
            for (int ni = 0; ni < 8; ni++) {
                uint32_t vh[2], vl[2];
                LDSM_X2T(vh, bb + FB_VH + vRel + ksp * (16 * FSTB) + ni * 16);
                LDSM_X2T(vl, bb + FB_VL + vRel + ksp * (16 * FSTB) + ni * 16);
                MMA16816(O[ni], pah, vh);
                MMA16816(O[ni], pah, vl);
                MMA16816(O[ni], pal, vh);
            }
        }

        CP_WAIT0();
        __syncthreads();
    }

    // ---- Final normalize + store ----
    const float ri0 = 1.f / l0r;
    const float ri1 = 1.f / l1r;
    float* C0 = ctx + (bS + r0g) * D_ + h * DK_;
    float* C1 = ctx + (bS + r1g) * D_ + h * DK_;
#pragma unroll
    for (int ni = 0; ni < 8; ni++) {
        const int c = ni * 8 + t * 2;
        float2 o0, o1;
        o0.x = O[ni][0] * ri0; o0.y = O[ni][1] * ri0;
        o1.x = O[ni][2] * ri1; o1.y = O[ni][3] * ri1;
        *(float2*)(C0 + c) = o0;
        *(float2*)(C1 + c) = o1;
    }
}

// ---------------------------------------------------------------------------
// Launch
// ---------------------------------------------------------------------------
extern "C" void kernel_launch(void* const* d_in, const int* in_sizes, int n_in,
                              void* d_out, int out_size)
{
    const float* query = (const float*)d_in[0];
    const float* key   = (const float*)d_in[1];
    const float* value = (const float*)d_in[2];
    const int*   mask  = (const int*)d_in[3];
    const float* w_q = (const float*)d_in[4];
    const float* b_q = (const float*)d_in[5];
    const float* w_k = (const float*)d_in[6];
    const float* b_k = (const float*)d_in[7];
    const float* w_v = (const float*)d_in[8];
    const float* b_v = (const float*)d_in[9];
    const float* w_o = (const float*)d_in[10];
    const float* b_o = (const float*)d_in[11];

    __nv_bfloat16 *qh, *ql, *kh, *kl, *vh, *vl;
    float *gc;
    cudaGetSymbolAddress((void**)&qh, g_qh);
    cudaGetSymbolAddress((void**)&ql, g_ql);
    cudaGetSymbolAddress((void**)&kh, g_kh);
    cudaGetSymbolAddress((void**)&kl, g_kl);
    cudaGetSymbolAddress((void**)&vh, g_vh);
    cudaGetSymbolAddress((void**)&vl, g_vl);
    cudaGetSymbolAddress((void**)&gc, g_ctx);

    cudaFuncSetAttribute(gemm_split,
                         cudaFuncAttributeMaxDynamicSharedMemorySize,
                         GEMM_SMEM);
    cudaFuncSetAttribute(gemm_f32,
                         cudaFuncAttributeMaxDynamicSharedMemorySize,
                         GEMM_SMEM);
    cudaFuncSetAttribute(flash_tc,
                         cudaFuncAttributeMaxDynamicSharedMemorySize,
                         FLASH_SMEM);

    const int M = B_ * S_;                        // 4096

    // Fused QKV projections: grid.z selects (A, W, bias, out) tuple.
    dim3 gqkv(D_ / 128, M / 128, 3);              // 768 CTAs
    gemm_split<<<gqkv, 256, GEMM_SMEM>>>(
        query, key, value,
        w_q, w_k, w_v,
        b_q, b_k, b_v,
        qh, kh, vh,
        ql, kl, vl,
        M, D_, D_);

    dim3 gflash(S_ / 128, H_, B_);                // 512 CTAs
    flash_tc<<<gflash, 256, FLASH_SMEM>>>(qh, ql, kh, kl, vh, vl, mask, gc);

    dim3 gproj(D_ / 128, M / 128);
    gemm_f32<<<gproj, 256, GEMM_SMEM>>>(gc, w_o, b_o, (float*)d_out, M, D_, D_);
}